// round 15
// baseline (speedup 1.0000x reference)
#include <cuda_runtime.h>

// MultiBCE collapsed form (validated R1/R9 shape; single change: 2x occupancy):
//   total = sum_{b,c} e(b,c) * w(c)
//   e(b,c) = -max(log(1 - |y_true - y_pred|), -100)   (y_true in {0,1})
//   w(c)   = (1/C) * sum_h lam[h] * La[h,c]
// Masked entries (La=0) contribute exactly 0 via the log clamp.
//
// Grid-stride loop keeps loads inside the loop (low MLP_p1 -> low multi-CTA
// completion spread, the mechanism that sank all front-batched variants).
// 1184 blocks = 8 CTAs/SM (64 warps, was 32): doubles SM-wide load
// parallelism to push the 40.6% DRAM utilization up.

#define BB 512
#define HH 8
#define CC 8192

#define NBLK 1184            // 8 CTAs/SM on 148 SMs (regs=25 -> fits)
#define NTHR 256

__device__ float g_wneg[CC];  // -w(c): acc = fma(clamped_log, wneg, acc)

__global__ void prep_kernel(const float* __restrict__ La,
                            const float* __restrict__ lam,
                            float* __restrict__ out) {
    int c = blockIdx.x * blockDim.x + threadIdx.x;
    if (c == 0) *out = 0.0f;  // d_out is poisoned; zero before atomics
    if (c < CC) {
        float s = 0.0f;
#pragma unroll
        for (int h = 0; h < HH; ++h)
            s += lam[h] * La[h * CC + c];
        g_wneg[c] = -s * (1.0f / (float)CC);
    }
}

__global__ void __launch_bounds__(NTHR)
bce_reduce_kernel(const float4* __restrict__ yp4,
                  const float4* __restrict__ yt4,
                  float* __restrict__ out) {
    const int N4 = (BB * CC) / 4;               // 1,048,576 float4 groups
    const float4* __restrict__ w4 = (const float4*)g_wneg;

    float acc = 0.0f;
    for (int i = blockIdx.x * blockDim.x + threadIdx.x; i < N4;
         i += gridDim.x * blockDim.x) {
        float4 p = yp4[i];
        float4 t = yt4[i];
        float4 w = w4[i & (CC / 4 - 1)];        // column index = i mod 2048

        // arg = 1 - |t - p| == t ? p : 1-p  (exact for t in {0,1}, p in [0,1))
        float a0 = 1.0f - fabsf(t.x - p.x);
        float a1 = 1.0f - fabsf(t.y - p.y);
        float a2 = 1.0f - fabsf(t.z - p.z);
        float a3 = 1.0f - fabsf(t.w - p.w);

        // __logf(0) = -inf -> fmaxf gives -100, matching the torch clamp.
        float l0 = fmaxf(__logf(a0), -100.0f);
        float l1 = fmaxf(__logf(a1), -100.0f);
        float l2 = fmaxf(__logf(a2), -100.0f);
        float l3 = fmaxf(__logf(a3), -100.0f);

        acc = fmaf(l0, w.x, acc);
        acc = fmaf(l1, w.y, acc);
        acc = fmaf(l2, w.z, acc);
        acc = fmaf(l3, w.w, acc);
    }

    // warp reduce
#pragma unroll
    for (int o = 16; o > 0; o >>= 1)
        acc += __shfl_down_sync(0xFFFFFFFFu, acc, o);

    __shared__ float smem[NTHR / 32];
    const int lane = threadIdx.x & 31;
    const int wid  = threadIdx.x >> 5;
    if (lane == 0) smem[wid] = acc;
    __syncthreads();
    if (wid == 0) {
        acc = (lane < NTHR / 32) ? smem[lane] : 0.0f;
#pragma unroll
        for (int o = 4; o > 0; o >>= 1)
            acc += __shfl_down_sync(0xFFFFFFFFu, acc, o);
        if (lane == 0) atomicAdd(out, acc);
    }
}

extern "C" void kernel_launch(void* const* d_in, const int* in_sizes, int n_in,
                              void* d_out, int out_size) {
    const float* y_pred = (const float*)d_in[0];  // [512, 8192] f32
    const float* y_true = (const float*)d_in[1];  // [512, 8192] f32
    const float* La     = (const float*)d_in[2];  // [8, 8192]   f32
    const float* lam    = (const float*)d_in[3];  // [8]         f32
    float* out = (float*)d_out;

    prep_kernel<<<(CC + 255) / 256, 256>>>(La, lam, out);

    // 1184 blocks = 8 CTAs/SM; grid-stride loop, ~3.5 iters/thread.
    bce_reduce_kernel<<<NBLK, NTHR>>>((const float4*)y_pred,
                                      (const float4*)y_true, out);
}